// round 16
// baseline (speedup 1.0000x reference)
#include <cuda_runtime.h>
#include <cuda_bf16.h>
#include <cstdint>

#define Tn 512
#define Bn 128
#define Hn 1024
#define Vn 256
#define En 512
#define HP 512               // packed pairs per row (Hn/2)
#define STEPW (Bn * HP)      // uint2 per step (65536)

typedef __nv_bfloat16 bf16;

// h / normed stored in MMA-fragment block layout:
//   block = 8 rows x 4 pairs = 32 uint2 (256B), uint2 = {hi(k),hi(k+1)|lo(k),lo(k+1)}
__device__ uint2 g_h1p[(size_t)Tn * Bn * HP];
__device__ uint2 g_h2p[(size_t)Tn * Bn * HP];
__device__ uint2 g_nmp[(size_t)Tn * Bn * HP];
__device__ float g_xp1[(size_t)Tn * Bn * Hn];
__device__ float g_xpe[Vn * Hn];
__device__ uint2 g_wh0p[Hn * HP];
__device__ uint2 g_wh1p[Hn * HP];
__device__ uint2 g_wi1p[Hn * HP];
__device__ uint2 g_pwp [Vn * HP];

// dataflow flags: (layer, group, bx) -> steps completed; 128B-strided
__device__ unsigned g_flag[2 * 4 * 32 * 32];

// ---------------- helpers ---------------------------------------------------
__device__ __forceinline__ void mma_bf16(float* c,
    uint32_t a0, uint32_t a1, uint32_t a2, uint32_t a3,
    uint32_t b0, uint32_t b1)
{
    asm volatile(
        "mma.sync.aligned.m16n8k16.row.col.f32.bf16.bf16.f32 "
        "{%0,%1,%2,%3}, {%4,%5,%6,%7}, {%8,%9}, {%0,%1,%2,%3};\n"
        : "+f"(c[0]), "+f"(c[1]), "+f"(c[2]), "+f"(c[3])
        : "r"(a0), "r"(a1), "r"(a2), "r"(a3), "r"(b0), "r"(b1));
}

__device__ __forceinline__ float tanh_fast(float x) {
    float e = __expf(2.f * x);
    return 1.f - __fdividef(2.f, e + 1.f);
}

// ---------------- flag reset (replay safety) --------------------------------
__global__ void reset_flags_kernel()
{
    int i = blockIdx.x * 256 + threadIdx.x;
    if (i < 2 * 4 * 32 * 32) g_flag[i] = 0u;
}

// ---------------- weight splitting into packed hi/lo ------------------------
__global__ void split_pack_kernel(const float* __restrict__ src,
                                  uint2* __restrict__ dst, int npairs)
{
    int p = blockIdx.x * 256 + threadIdx.x;
    if (p < npairs) {
        float v0 = src[2 * p], v1 = src[2 * p + 1];
        bf16 h0 = __float2bfloat16(v0);
        bf16 l0 = __float2bfloat16(v0 - __bfloat162float(h0));
        bf16 h1 = __float2bfloat16(v1);
        bf16 l1 = __float2bfloat16(v1 - __bfloat162float(h1));
        __nv_bfloat162 hi; hi.x = h0; hi.y = h1;
        __nv_bfloat162 lo; lo.x = l0; lo.y = l1;
        uint2 o;
        o.x = *reinterpret_cast<uint32_t*>(&hi);
        o.y = *reinterpret_cast<uint32_t*>(&lo);
        dst[p] = o;
    }
}

// ---------------- xpe[v][h] = Wi0 @ emb[v] + bi0 (fp32) ---------------------
__global__ void __launch_bounds__(256) xpe_kernel(
    const float* __restrict__ emb, const float* __restrict__ wi0,
    const float* __restrict__ bi0, float* __restrict__ xpe)
{
    __shared__ float se[16][33];
    __shared__ float sw[64][33];
    int vbase = blockIdx.x * 16, hbase = blockIdx.y * 64;
    int tid = threadIdx.x;
    int vl = tid >> 4;
    int hl = (tid & 15) * 4;
    float acc[4] = {0.f, 0.f, 0.f, 0.f};
    for (int k0 = 0; k0 < En; k0 += 32) {
        for (int i = tid; i < 16 * 32; i += 256)
            se[i >> 5][i & 31] = emb[(size_t)(vbase + (i >> 5)) * En + k0 + (i & 31)];
        for (int i = tid; i < 64 * 32; i += 256)
            sw[i >> 5][i & 31] = wi0[(size_t)(hbase + (i >> 5)) * En + k0 + (i & 31)];
        __syncthreads();
#pragma unroll
        for (int kk = 0; kk < 32; kk++) {
            float a = se[vl][kk];
            acc[0] += a * sw[hl + 0][kk];
            acc[1] += a * sw[hl + 1][kk];
            acc[2] += a * sw[hl + 2][kk];
            acc[3] += a * sw[hl + 3][kk];
        }
        __syncthreads();
    }
#pragma unroll
    for (int p = 0; p < 4; p++)
        xpe[(size_t)(vbase + vl) * Hn + hbase + hl + p] = acc[p] + bi0[hbase + hl + p];
}

// ---------------- persistent scan: 16 warps, K-slice 64/warp (R15 winner) ---
#define SCAN_SMEM_BYTES (16 * 1152 * 8 + 16 * 1152 * 4)

__global__ void __launch_bounds__(512, 1) scan_reg_kernel(
    const uint2* __restrict__ Wp, uint2* __restrict__ hseq,
    const float* __restrict__ xp, const int* __restrict__ x, int layer)
{
    extern __shared__ uint2 sm2[];
    uint2* sW = sm2;                                       // 16*1152 uint2
    float* sRed = reinterpret_cast<float*>(sm2 + 16 * 1152);

    int tid = threadIdx.x, lane = tid & 31, warp = tid >> 5;
    int g = lane >> 2, tq = lane & 3;
    int nbase = blockIdx.x * 32;
    int ga = blockIdx.y;             // batch group 0..3
    int mbase = ga * 32;

    unsigned* myflag = &g_flag[(((unsigned)layer * 4 + ga) * 32 + blockIdx.x) * 32];
    const unsigned* pf0 = &g_flag[(((unsigned)layer * 4 + ga) * 32 + (warp * 2)) * 32];
    const unsigned* pf1 = &g_flag[(((unsigned)layer * 4 + ga) * 32 + (warp * 2 + 1)) * 32];

    for (int i = tid; i < 8192; i += 512) {
        int r = i >> 8;
        int pq = (i & 255) * 2;
        int ch = pq >> 5, q = pq & 31;
        *reinterpret_cast<uint4*>(&sW[ch * 1152 + r * 36 + q]) =
            *reinterpret_cast<const uint4*>(&Wp[(size_t)(nbase + r) * HP + pq]);
    }
    __syncthreads();

    int em = tid >> 4;
    int ep = tid & 15;
    int eb = mbase + em;
    int egc = nbase + ep * 2;
    int p0 = (nbase >> 1) + ep;
    size_t efo = (((size_t)(eb >> 3)) * 128 + (p0 >> 2)) * 32 + (eb & 7) * 4 + (p0 & 3);
    int rb0 = mbase >> 3;

    for (int t = 0; t < Tn; t++) {
        float2 xv;
        if (layer == 0) {
            int xi = x[(size_t)eb * Tn + t];
            xv = *reinterpret_cast<const float2*>(xp + (size_t)xi * Hn + egc);
        } else {
            xv = *reinterpret_cast<const float2*>(xp + ((size_t)t * Bn + eb) * Hn + egc);
        }

        float o0 = 0.f, o1 = 0.f;

        if (t > 0) {
            const uint2* At = hseq + (size_t)(t - 1) * STEPW;
            float acc[2][4][4] = {};
            unsigned tw = (unsigned)t;

            uint2 a_cur[2][4], a_nxt[2][4];
            {
                unsigned v;
                asm volatile("ld.acquire.gpu.global.u32 %0, [%1];"
                             : "=r"(v) : "l"(pf0) : "memory");
                while (v < tw) {
                    __nanosleep(20);
                    asm volatile("ld.acquire.gpu.global.u32 %0, [%1];"
                                 : "=r"(v) : "l"(pf0) : "memory");
                }
                const uint2* bp = At + ((size_t)rb0 * 128 + warp * 8) * 32;
#pragma unroll
                for (int mt = 0; mt < 2; mt++) {
                    const uint2* q = bp + mt * 8192;
                    a_cur[mt][0] = q[lane];
                    a_cur[mt][1] = q[4096 + lane];
                    a_cur[mt][2] = q[32 + lane];
                    a_cur[mt][3] = q[4096 + 32 + lane];
                }
            }

#pragma unroll
            for (int kk = 0; kk < 4; kk++) {
                if (kk < 3) {
                    if (kk + 1 == 2) {
                        unsigned v;
                        asm volatile("ld.acquire.gpu.global.u32 %0, [%1];"
                                     : "=r"(v) : "l"(pf1) : "memory");
                        while (v < tw) {
                            __nanosleep(20);
                            asm volatile("ld.acquire.gpu.global.u32 %0, [%1];"
                                         : "=r"(v) : "l"(pf1) : "memory");
                        }
                    }
                    int pbb = warp * 8 + (kk + 1) * 2;
                    const uint2* bp = At + ((size_t)rb0 * 128 + pbb) * 32;
#pragma unroll
                    for (int mt = 0; mt < 2; mt++) {
                        const uint2* q = bp + mt * 8192;
                        a_nxt[mt][0] = q[lane];
                        a_nxt[mt][1] = q[4096 + lane];
                        a_nxt[mt][2] = q[32 + lane];
                        a_nxt[mt][3] = q[4096 + 32 + lane];
                    }
                }

                const uint2* wch = sW + warp * 1152;
                int q = kk * 8 + tq;
#pragma unroll
                for (int j = 0; j < 4; j++) {
                    uint2 b0 = wch[(j * 8 + g) * 36 + q];
                    uint2 b1 = wch[(j * 8 + g) * 36 + q + 4];
#pragma unroll
                    for (int mt = 0; mt < 2; mt++) {
                        mma_bf16(acc[mt][j], a_cur[mt][0].x, a_cur[mt][1].x, a_cur[mt][2].x, a_cur[mt][3].x, b0.x, b1.x);
                        mma_bf16(acc[mt][j], a_cur[mt][0].x, a_cur[mt][1].x, a_cur[mt][2].x, a_cur[mt][3].x, b0.y, b1.y);
                        mma_bf16(acc[mt][j], a_cur[mt][0].y, a_cur[mt][1].y, a_cur[mt][2].y, a_cur[mt][3].y, b0.x, b1.x);
                    }
                }

                if (kk < 3) {
#pragma unroll
                    for (int mt = 0; mt < 2; mt++)
#pragma unroll
                        for (int j = 0; j < 4; j++)
                            a_cur[mt][j] = a_nxt[mt][j];
                }
            }

            float* pr = sRed + warp * 1152;
#pragma unroll
            for (int mt = 0; mt < 2; mt++)
#pragma unroll
                for (int j = 0; j < 4; j++) {
                    int r0 = mt * 16 + g, cc = j * 8 + 2 * tq;
                    *reinterpret_cast<float2*>(&pr[r0 * 36 + cc]) =
                        make_float2(acc[mt][j][0], acc[mt][j][1]);
                    *reinterpret_cast<float2*>(&pr[(r0 + 8) * 36 + cc]) =
                        make_float2(acc[mt][j][2], acc[mt][j][3]);
                }
            __syncthreads();
#pragma unroll
            for (int w = 0; w < 16; w++) {
                float2 p = *reinterpret_cast<const float2*>(&sRed[w * 1152 + em * 36 + ep * 2]);
                o0 += p.x; o1 += p.y;
            }
        }

        {
            float v0 = tanh_fast(o0 + xv.x);
            float v1 = tanh_fast(o1 + xv.y);
            bf16 h0 = __float2bfloat16(v0);
            bf16 l0 = __float2bfloat16(v0 - __bfloat162float(h0));
            bf16 h1 = __float2bfloat16(v1);
            bf16 l1 = __float2bfloat16(v1 - __bfloat162float(h1));
            __nv_bfloat162 hi; hi.x = h0; hi.y = h1;
            __nv_bfloat162 lo; lo.x = l0; lo.y = l1;
            uint2 o;
            o.x = *reinterpret_cast<uint32_t*>(&hi);
            o.y = *reinterpret_cast<uint32_t*>(&lo);
            hseq[(size_t)t * STEPW + efo] = o;
        }

        __syncthreads();
        if (tid == 0) {
            asm volatile("fence.acq_rel.gpu;" ::: "memory");
            asm volatile("red.relaxed.gpu.global.add.u32 [%0], %1;"
                         :: "l"(myflag), "r"(1u) : "memory");
        }
    }
}

// ---------------- big parallel GEMM: 128x128 tile, 512 threads --------------
// Warp tile 32x32 (16 warps, 4x4 grid). MMA:LDS.64 ratio 24:16 per warp-kki.
// A in fragment-block layout; B row-major packed.
#define GEMM_SMEM_BYTES (2 * 128 * 36 * 8)

__global__ void __launch_bounds__(512, 1) gemm_split_kernel(
    const uint2* __restrict__ Ap, const uint2* __restrict__ Wp,
    const float* __restrict__ bias, float* __restrict__ outf, int mode)
{
    extern __shared__ uint2 gsm[];
    uint2* sA = gsm;                 // [128][36]
    uint2* sB = gsm + 128 * 36;      // [128][36]

    int tid = threadIdx.x, lane = tid & 31, warp = tid >> 5;
    int wm = warp & 3, wn = warp >> 2;           // 4 x 4 warp grid
    int mbase = blockIdx.x * 128, nbase = blockIdx.y * 128;
    int mb0 = mbase >> 3;
    int g = lane >> 2, tq = lane & 3;
    float c[2][4][4] = {};

    for (int k0 = 0; k0 < HP; k0 += 32) {
        int pb0 = k0 >> 2;
#pragma unroll
        for (int i = 0; i < 4; i++) {
            int idx = tid + i * 512;              // 0..2047
            // A gather from fragment blocks (coalesced 16B per thread)
            int rb = idx >> 7, pbi = (idx >> 4) & 7, op = (idx & 15) * 2;
            int rl = rb * 8 + (op >> 2), plc = pbi * 4 + (op & 3);
            *reinterpret_cast<uint4*>(&sA[rl * 36 + plc]) =
                *reinterpret_cast<const uint4*>(
                    &Ap[(((size_t)(mb0 + rb)) * 128 + pb0 + pbi) * 32 + op]);
            // B row-major
            int r = idx >> 4, q = (idx & 15) * 2;
            *reinterpret_cast<uint4*>(&sB[r * 36 + q]) =
                *reinterpret_cast<const uint4*>(&Wp[(size_t)(nbase + r) * HP + k0 + q]);
        }
        __syncthreads();
#pragma unroll
        for (int kki = 0; kki < 4; kki++) {
            int bp = kki * 8 + tq;
            uint2 a0[2], a1[2], a2[2], a3[2];
#pragma unroll
            for (int mt = 0; mt < 2; mt++) {
                int ar = wm * 32 + mt * 16 + g;
                a0[mt] = sA[ar * 36 + bp];
                a1[mt] = sA[(ar + 8) * 36 + bp];
                a2[mt] = sA[ar * 36 + bp + 4];
                a3[mt] = sA[(ar + 8) * 36 + bp + 4];
            }
#pragma unroll
            for (int j = 0; j < 4; j++) {
                int br = wn * 32 + j * 8 + g;
                uint2 b0 = sB[br * 36 + bp];
                uint2 b1 = sB[br * 36 + bp + 4];
#pragma unroll
                for (int mt = 0; mt < 2; mt++) {
                    mma_bf16(c[mt][j], a0[mt].x, a1[mt].x, a2[mt].x, a3[mt].x, b0.x, b1.x);
                    mma_bf16(c[mt][j], a0[mt].x, a1[mt].x, a2[mt].x, a3[mt].x, b0.y, b1.y);
                    mma_bf16(c[mt][j], a0[mt].y, a1[mt].y, a2[mt].y, a3[mt].y, b0.x, b1.x);
                }
            }
        }
        __syncthreads();
    }

#pragma unroll
    for (int mt = 0; mt < 2; mt++)
#pragma unroll
        for (int j = 0; j < 4; j++)
#pragma unroll
            for (int rh = 0; rh < 2; rh++) {
                int m = mbase + wm * 32 + mt * 16 + g + rh * 8;
                int n = nbase + wn * 32 + j * 8 + 2 * tq;
                float v0 = c[mt][j][rh * 2 + 0] + bias[n];
                float v1 = c[mt][j][rh * 2 + 1] + bias[n + 1];
                if (mode == 0) {
                    outf[(size_t)m * Hn + n] = v0;
                    outf[(size_t)m * Hn + n + 1] = v1;
                } else {
                    int b = m & (Bn - 1), t = m >> 7;
                    size_t o = ((size_t)b * Tn + t) * Vn + n;
                    outf[o] = v0;
                    outf[o + 1] = v1;
                }
            }
}

// ---------------- layernorm (fragment layout in/out) ------------------------
__global__ void __launch_bounds__(256) ln_kernel(
    const uint2* __restrict__ hp, const float* __restrict__ gam,
    const float* __restrict__ bet, uint2* __restrict__ nm)
{
    __shared__ float red[18];
    size_t row = blockIdx.x;
    int tid = threadIdx.x;
    int c0 = tid * 4;
    int p0 = tid * 2;
    size_t fo = (((size_t)(row >> 3)) * 128 + (p0 >> 2)) * 32 + ((int)row & 7) * 4 + (p0 & 3);

    uint4 in = *reinterpret_cast<const uint4*>(&hp[fo]);
    const __nv_bfloat162* pcs = reinterpret_cast<const __nv_bfloat162*>(&in);
    float v[4];
    v[0] = __bfloat162float(pcs[0].x) + __bfloat162float(pcs[1].x);
    v[1] = __bfloat162float(pcs[0].y) + __bfloat162float(pcs[1].y);
    v[2] = __bfloat162float(pcs[2].x) + __bfloat162float(pcs[3].x);
    v[3] = __bfloat162float(pcs[2].y) + __bfloat162float(pcs[3].y);

    float s = 0.f, q = 0.f;
#pragma unroll
    for (int i = 0; i < 4; i++) { s += v[i]; q += v[i] * v[i]; }
#pragma unroll
    for (int o = 16; o; o >>= 1) {
        s += __shfl_xor_sync(0xffffffffu, s, o);
        q += __shfl_xor_sync(0xffffffffu, q, o);
    }
    int warp = tid >> 5, lane = tid & 31;
    if (lane == 0) { red[warp] = s; red[warp + 8] = q; }
    __syncthreads();
    if (tid == 0) {
        float ss = 0.f, qq = 0.f;
#pragma unroll
        for (int i = 0; i < 8; i++) { ss += red[i]; qq += red[i + 8]; }
        float mu = ss / (float)Hn;
        float var = qq / (float)Hn - mu * mu;
        red[16] = mu;
        red[17] = rsqrtf(var + 1e-5f);
    }
    __syncthreads();
    float mu = red[16], rstd = red[17];

    bf16 hh[4], ll[4];
#pragma unroll
    for (int i = 0; i < 4; i++) {
        float nv = (v[i] - mu) * rstd * gam[c0 + i] + bet[c0 + i];
        hh[i] = __float2bfloat16(nv);
        ll[i] = __float2bfloat16(nv - __bfloat162float(hh[i]));
    }
    union { uint4 q4; __nv_bfloat162 h2[4]; } U;
    U.h2[0].x = hh[0]; U.h2[0].y = hh[1];
    U.h2[1].x = ll[0]; U.h2[1].y = ll[1];
    U.h2[2].x = hh[2]; U.h2[2].y = hh[3];
    U.h2[3].x = ll[2]; U.h2[3].y = ll[3];
    *reinterpret_cast<uint4*>(&nm[fo]) = U.q4;
}

// ---------------- launch ------------------------------------------------------
extern "C" void kernel_launch(void* const* d_in, const int* in_sizes, int n_in,
                              void* d_out, int out_size)
{
    const float* emb    = (const float*)d_in[0];
    const float* wi0    = (const float*)d_in[1];
    const float* bi0    = (const float*)d_in[2];
    const float* wh0    = (const float*)d_in[3];
    const float* wi1    = (const float*)d_in[4];
    const float* bi1    = (const float*)d_in[5];
    const float* wh1    = (const float*)d_in[6];
    const float* ln_g   = (const float*)d_in[7];
    const float* ln_b   = (const float*)d_in[8];
    const float* proj_w = (const float*)d_in[9];
    const float* proj_b = (const float*)d_in[10];
    const int*   x      = (const int*)d_in[11];

    uint2 *h1p, *h2p, *nmp, *wh0p, *wh1p, *wi1p, *pwp;
    float *xp1, *xpe;
    cudaGetSymbolAddress((void**)&h1p,  g_h1p);
    cudaGetSymbolAddress((void**)&h2p,  g_h2p);
    cudaGetSymbolAddress((void**)&nmp,  g_nmp);
    cudaGetSymbolAddress((void**)&wh0p, g_wh0p);
    cudaGetSymbolAddress((void**)&wh1p, g_wh1p);
    cudaGetSymbolAddress((void**)&wi1p, g_wi1p);
    cudaGetSymbolAddress((void**)&pwp,  g_pwp);
    cudaGetSymbolAddress((void**)&xp1,  g_xp1);
    cudaGetSymbolAddress((void**)&xpe,  g_xpe);

    cudaFuncSetAttribute(scan_reg_kernel,
                         cudaFuncAttributeMaxDynamicSharedMemorySize,
                         SCAN_SMEM_BYTES);
    cudaFuncSetAttribute(gemm_split_kernel,
                         cudaFuncAttributeMaxDynamicSharedMemorySize,
                         GEMM_SMEM_BYTES);

    // [0] flag reset (replay safety for the dataflow flags)
    reset_flags_kernel<<<(2 * 4 * 32 * 32 + 255) / 256, 256>>>();
    // [1],[2] setup; [3] scan0 (kept at ncu's profiled slot)
    split_pack_kernel<<<(Hn * HP + 255) / 256, 256>>>(wh0, wh0p, Hn * HP);
    xpe_kernel<<<dim3(16, 16), 256>>>(emb, wi0, bi0, xpe);

    scan_reg_kernel<<<dim3(32, 4), 512, SCAN_SMEM_BYTES>>>(
        wh0p, h1p, xpe, x, 0);

    split_pack_kernel<<<(Hn * HP + 255) / 256, 256>>>(wi1, wi1p, Hn * HP);
    gemm_split_kernel<<<dim3(512, 8), 512, GEMM_SMEM_BYTES>>>(h1p, wi1p, bi1, xp1, 0);

    split_pack_kernel<<<(Hn * HP + 255) / 256, 256>>>(wh1, wh1p, Hn * HP);
    scan_reg_kernel<<<dim3(32, 4), 512, SCAN_SMEM_BYTES>>>(
        wh1p, h2p, xp1, x, 1);

    split_pack_kernel<<<(Vn * HP + 255) / 256, 256>>>(proj_w, pwp, Vn * HP);
    ln_kernel<<<Tn * Bn, 256>>>(h2p, ln_g, ln_b, nmp);
    gemm_split_kernel<<<dim3(512, 2), 512, GEMM_SMEM_BYTES>>>(nmp, pwp, proj_b, (float*)d_out, 1);
}

// round 17
// speedup vs baseline: 1.0427x; 1.0427x over previous
#include <cuda_runtime.h>
#include <cuda_bf16.h>
#include <cstdint>

#define Tn 512
#define Bn 128
#define Hn 1024
#define Vn 256
#define En 512
#define HP 512               // packed pairs per row (Hn/2)
#define STEPW (Bn * HP)      // uint2 per step (65536)

typedef __nv_bfloat16 bf16;

// h / normed stored in MMA-fragment block layout:
//   block = 8 rows x 4 pairs = 32 uint2 (256B), uint2 = {hi(k),hi(k+1)|lo(k),lo(k+1)}
__device__ uint2 g_h1p[(size_t)Tn * Bn * HP];
__device__ uint2 g_h2p[(size_t)Tn * Bn * HP];
__device__ uint2 g_nmp[(size_t)Tn * Bn * HP];
__device__ float g_xp1[(size_t)Tn * Bn * Hn];
__device__ float g_xpe[Vn * Hn];
__device__ uint2 g_wh0p[Hn * HP];
__device__ uint2 g_wh1p[Hn * HP];
__device__ uint2 g_wi1p[Hn * HP];
__device__ uint2 g_pwp [Vn * HP];

// dataflow flags: (layer, group, bx) -> steps completed; 128B-strided
__device__ unsigned g_flag[2 * 4 * 32 * 32];

// ---------------- helpers ---------------------------------------------------
__device__ __forceinline__ void mma_bf16(float* c,
    uint32_t a0, uint32_t a1, uint32_t a2, uint32_t a3,
    uint32_t b0, uint32_t b1)
{
    asm volatile(
        "mma.sync.aligned.m16n8k16.row.col.f32.bf16.bf16.f32 "
        "{%0,%1,%2,%3}, {%4,%5,%6,%7}, {%8,%9}, {%0,%1,%2,%3};\n"
        : "+f"(c[0]), "+f"(c[1]), "+f"(c[2]), "+f"(c[3])
        : "r"(a0), "r"(a1), "r"(a2), "r"(a3), "r"(b0), "r"(b1));
}

__device__ __forceinline__ float tanh_fast(float x) {
    float e = __expf(2.f * x);
    return 1.f - __fdividef(2.f, e + 1.f);
}

// ---------------- flag reset (replay safety) --------------------------------
__global__ void reset_flags_kernel()
{
    int i = blockIdx.x * 256 + threadIdx.x;
    if (i < 2 * 4 * 32 * 32) g_flag[i] = 0u;
}

// ---------------- weight splitting into packed hi/lo ------------------------
__global__ void split_pack_kernel(const float* __restrict__ src,
                                  uint2* __restrict__ dst, int npairs)
{
    int p = blockIdx.x * 256 + threadIdx.x;
    if (p < npairs) {
        float v0 = src[2 * p], v1 = src[2 * p + 1];
        bf16 h0 = __float2bfloat16(v0);
        bf16 l0 = __float2bfloat16(v0 - __bfloat162float(h0));
        bf16 h1 = __float2bfloat16(v1);
        bf16 l1 = __float2bfloat16(v1 - __bfloat162float(h1));
        __nv_bfloat162 hi; hi.x = h0; hi.y = h1;
        __nv_bfloat162 lo; lo.x = l0; lo.y = l1;
        uint2 o;
        o.x = *reinterpret_cast<uint32_t*>(&hi);
        o.y = *reinterpret_cast<uint32_t*>(&lo);
        dst[p] = o;
    }
}

// ---------------- xpe[v][h] = Wi0 @ emb[v] + bi0 (fp32) ---------------------
__global__ void __launch_bounds__(256) xpe_kernel(
    const float* __restrict__ emb, const float* __restrict__ wi0,
    const float* __restrict__ bi0, float* __restrict__ xpe)
{
    __shared__ float se[16][33];
    __shared__ float sw[64][33];
    int vbase = blockIdx.x * 16, hbase = blockIdx.y * 64;
    int tid = threadIdx.x;
    int vl = tid >> 4;
    int hl = (tid & 15) * 4;
    float acc[4] = {0.f, 0.f, 0.f, 0.f};
    for (int k0 = 0; k0 < En; k0 += 32) {
        for (int i = tid; i < 16 * 32; i += 256)
            se[i >> 5][i & 31] = emb[(size_t)(vbase + (i >> 5)) * En + k0 + (i & 31)];
        for (int i = tid; i < 64 * 32; i += 256)
            sw[i >> 5][i & 31] = wi0[(size_t)(hbase + (i >> 5)) * En + k0 + (i & 31)];
        __syncthreads();
#pragma unroll
        for (int kk = 0; kk < 32; kk++) {
            float a = se[vl][kk];
            acc[0] += a * sw[hl + 0][kk];
            acc[1] += a * sw[hl + 1][kk];
            acc[2] += a * sw[hl + 2][kk];
            acc[3] += a * sw[hl + 3][kk];
        }
        __syncthreads();
    }
#pragma unroll
    for (int p = 0; p < 4; p++)
        xpe[(size_t)(vbase + vl) * Hn + hbase + hl + p] = acc[p] + bi0[hbase + hl + p];
}

// ---------------- persistent scan: 16 warps, K-slice 64/warp (R15 winner) ---
#define SCAN_SMEM_BYTES (16 * 1152 * 8 + 16 * 1152 * 4)

__global__ void __launch_bounds__(512, 1) scan_reg_kernel(
    const uint2* __restrict__ Wp, uint2* __restrict__ hseq,
    const float* __restrict__ xp, const int* __restrict__ x, int layer)
{
    extern __shared__ uint2 sm2[];
    uint2* sW = sm2;                                       // 16*1152 uint2
    float* sRed = reinterpret_cast<float*>(sm2 + 16 * 1152);

    int tid = threadIdx.x, lane = tid & 31, warp = tid >> 5;
    int g = lane >> 2, tq = lane & 3;
    int nbase = blockIdx.x * 32;
    int ga = blockIdx.y;             // batch group 0..3
    int mbase = ga * 32;

    unsigned* myflag = &g_flag[(((unsigned)layer * 4 + ga) * 32 + blockIdx.x) * 32];
    const unsigned* pf0 = &g_flag[(((unsigned)layer * 4 + ga) * 32 + (warp * 2)) * 32];
    const unsigned* pf1 = &g_flag[(((unsigned)layer * 4 + ga) * 32 + (warp * 2 + 1)) * 32];

    for (int i = tid; i < 8192; i += 512) {
        int r = i >> 8;
        int pq = (i & 255) * 2;
        int ch = pq >> 5, q = pq & 31;
        *reinterpret_cast<uint4*>(&sW[ch * 1152 + r * 36 + q]) =
            *reinterpret_cast<const uint4*>(&Wp[(size_t)(nbase + r) * HP + pq]);
    }
    __syncthreads();

    int em = tid >> 4;
    int ep = tid & 15;
    int eb = mbase + em;
    int egc = nbase + ep * 2;
    int p0 = (nbase >> 1) + ep;
    size_t efo = (((size_t)(eb >> 3)) * 128 + (p0 >> 2)) * 32 + (eb & 7) * 4 + (p0 & 3);
    int rb0 = mbase >> 3;

    for (int t = 0; t < Tn; t++) {
        float2 xv;
        if (layer == 0) {
            int xi = x[(size_t)eb * Tn + t];
            xv = *reinterpret_cast<const float2*>(xp + (size_t)xi * Hn + egc);
        } else {
            xv = *reinterpret_cast<const float2*>(xp + ((size_t)t * Bn + eb) * Hn + egc);
        }

        float o0 = 0.f, o1 = 0.f;

        if (t > 0) {
            const uint2* At = hseq + (size_t)(t - 1) * STEPW;
            float acc[2][4][4] = {};
            unsigned tw = (unsigned)t;

            uint2 a_cur[2][4], a_nxt[2][4];
            {
                unsigned v;
                asm volatile("ld.acquire.gpu.global.u32 %0, [%1];"
                             : "=r"(v) : "l"(pf0) : "memory");
                while (v < tw) {
                    __nanosleep(20);
                    asm volatile("ld.acquire.gpu.global.u32 %0, [%1];"
                                 : "=r"(v) : "l"(pf0) : "memory");
                }
                const uint2* bp = At + ((size_t)rb0 * 128 + warp * 8) * 32;
#pragma unroll
                for (int mt = 0; mt < 2; mt++) {
                    const uint2* q = bp + mt * 8192;
                    a_cur[mt][0] = q[lane];
                    a_cur[mt][1] = q[4096 + lane];
                    a_cur[mt][2] = q[32 + lane];
                    a_cur[mt][3] = q[4096 + 32 + lane];
                }
            }

#pragma unroll
            for (int kk = 0; kk < 4; kk++) {
                if (kk < 3) {
                    if (kk + 1 == 2) {
                        unsigned v;
                        asm volatile("ld.acquire.gpu.global.u32 %0, [%1];"
                                     : "=r"(v) : "l"(pf1) : "memory");
                        while (v < tw) {
                            __nanosleep(20);
                            asm volatile("ld.acquire.gpu.global.u32 %0, [%1];"
                                         : "=r"(v) : "l"(pf1) : "memory");
                        }
                    }
                    int pbb = warp * 8 + (kk + 1) * 2;
                    const uint2* bp = At + ((size_t)rb0 * 128 + pbb) * 32;
#pragma unroll
                    for (int mt = 0; mt < 2; mt++) {
                        const uint2* q = bp + mt * 8192;
                        a_nxt[mt][0] = q[lane];
                        a_nxt[mt][1] = q[4096 + lane];
                        a_nxt[mt][2] = q[32 + lane];
                        a_nxt[mt][3] = q[4096 + 32 + lane];
                    }
                }

                const uint2* wch = sW + warp * 1152;
                int q = kk * 8 + tq;
#pragma unroll
                for (int j = 0; j < 4; j++) {
                    uint2 b0 = wch[(j * 8 + g) * 36 + q];
                    uint2 b1 = wch[(j * 8 + g) * 36 + q + 4];
#pragma unroll
                    for (int mt = 0; mt < 2; mt++) {
                        mma_bf16(acc[mt][j], a_cur[mt][0].x, a_cur[mt][1].x, a_cur[mt][2].x, a_cur[mt][3].x, b0.x, b1.x);
                        mma_bf16(acc[mt][j], a_cur[mt][0].x, a_cur[mt][1].x, a_cur[mt][2].x, a_cur[mt][3].x, b0.y, b1.y);
                        mma_bf16(acc[mt][j], a_cur[mt][0].y, a_cur[mt][1].y, a_cur[mt][2].y, a_cur[mt][3].y, b0.x, b1.x);
                    }
                }

                if (kk < 3) {
#pragma unroll
                    for (int mt = 0; mt < 2; mt++)
#pragma unroll
                        for (int j = 0; j < 4; j++)
                            a_cur[mt][j] = a_nxt[mt][j];
                }
            }

            float* pr = sRed + warp * 1152;
#pragma unroll
            for (int mt = 0; mt < 2; mt++)
#pragma unroll
                for (int j = 0; j < 4; j++) {
                    int r0 = mt * 16 + g, cc = j * 8 + 2 * tq;
                    *reinterpret_cast<float2*>(&pr[r0 * 36 + cc]) =
                        make_float2(acc[mt][j][0], acc[mt][j][1]);
                    *reinterpret_cast<float2*>(&pr[(r0 + 8) * 36 + cc]) =
                        make_float2(acc[mt][j][2], acc[mt][j][3]);
                }
            __syncthreads();
#pragma unroll
            for (int w = 0; w < 16; w++) {
                float2 p = *reinterpret_cast<const float2*>(&sRed[w * 1152 + em * 36 + ep * 2]);
                o0 += p.x; o1 += p.y;
            }
        }

        {
            float v0 = tanh_fast(o0 + xv.x);
            float v1 = tanh_fast(o1 + xv.y);
            bf16 h0 = __float2bfloat16(v0);
            bf16 l0 = __float2bfloat16(v0 - __bfloat162float(h0));
            bf16 h1 = __float2bfloat16(v1);
            bf16 l1 = __float2bfloat16(v1 - __bfloat162float(h1));
            __nv_bfloat162 hi; hi.x = h0; hi.y = h1;
            __nv_bfloat162 lo; lo.x = l0; lo.y = l1;
            uint2 o;
            o.x = *reinterpret_cast<uint32_t*>(&hi);
            o.y = *reinterpret_cast<uint32_t*>(&lo);
            hseq[(size_t)t * STEPW + efo] = o;
        }

        __syncthreads();
        if (tid == 0) {
            asm volatile("fence.acq_rel.gpu;" ::: "memory");
            asm volatile("red.relaxed.gpu.global.add.u32 [%0], %1;"
                         :: "l"(myflag), "r"(1u) : "memory");
        }
    }
}

// ---------------- big parallel GEMM: 64x64 tile, double-buffered smem -------
// 256 threads, 2 CTAs/SM. One __syncthreads per K-chunk: LDG(next)->regs,
// compute(cur buf), STS(next)->other buf, sync. LDG latency hides under MMAs.
__global__ void __launch_bounds__(256, 2) gemm_split_kernel(
    const uint2* __restrict__ Ap, const uint2* __restrict__ Wp,
    const float* __restrict__ bias, float* __restrict__ outf, int mode)
{
    __shared__ uint2 sA[2][64][36], sB[2][64][36];
    int tid = threadIdx.x, lane = tid & 31, warp = tid >> 5;
    int wm = warp & 3, wn = warp >> 2;
    int mbase = blockIdx.x * 64, nbase = blockIdx.y * 64;
    int mb0 = mbase >> 3;
    int g = lane >> 2, tq = lane & 3;
    float c[4][4] = {};

    // per-thread staging geometry (4 uint4 of A + 4 uint4 of B per chunk)
    int s_rb[4], s_pbi[4], s_op[4], s_rl[4], s_plc[4], s_r[4], s_q[4];
#pragma unroll
    for (int i = 0; i < 4; i++) {
        int idx = tid + i * 256;
        s_rb[i] = idx >> 7;
        s_pbi[i] = (idx >> 4) & 7;
        s_op[i] = (idx & 15) * 2;
        s_rl[i] = s_rb[i] * 8 + (s_op[i] >> 2);
        s_plc[i] = s_pbi[i] * 4 + (s_op[i] & 3);
        s_r[i] = idx >> 4;
        s_q[i] = (idx & 15) * 2;
    }

    uint4 pa[4], pb[4];
    // prologue: LDG chunk 0 -> regs; STS to buf 0; sync
#pragma unroll
    for (int i = 0; i < 4; i++) {
        pa[i] = *reinterpret_cast<const uint4*>(
            &Ap[(((size_t)(mb0 + s_rb[i])) * 128 + s_pbi[i]) * 32 + s_op[i]]);
        pb[i] = *reinterpret_cast<const uint4*>(
            &Wp[(size_t)(nbase + s_r[i]) * HP + s_q[i]]);
    }
#pragma unroll
    for (int i = 0; i < 4; i++) {
        *reinterpret_cast<uint4*>(&sA[0][s_rl[i]][s_plc[i]]) = pa[i];
        *reinterpret_cast<uint4*>(&sB[0][s_r[i]][s_q[i]]) = pb[i];
    }
    __syncthreads();

    for (int ch = 0; ch < 16; ch++) {
        int buf = ch & 1;
        // LDG next chunk (latency hides under compute below)
        if (ch < 15) {
            int k0 = (ch + 1) * 32;
            int pb0 = k0 >> 2;
#pragma unroll
            for (int i = 0; i < 4; i++) {
                pa[i] = *reinterpret_cast<const uint4*>(
                    &Ap[(((size_t)(mb0 + s_rb[i])) * 128 + pb0 + s_pbi[i]) * 32 + s_op[i]]);
                pb[i] = *reinterpret_cast<const uint4*>(
                    &Wp[(size_t)(nbase + s_r[i]) * HP + k0 + s_q[i]]);
            }
        }
        // compute current buffer
#pragma unroll
        for (int kki = 0; kki < 4; kki++) {
            int bp = kki * 8 + tq;
            int ar = wm * 16 + g;
            uint2 a0 = sA[buf][ar][bp];
            uint2 a1 = sA[buf][ar + 8][bp];
            uint2 a2 = sA[buf][ar][bp + 4];
            uint2 a3 = sA[buf][ar + 8][bp + 4];
#pragma unroll
            for (int j = 0; j < 4; j++) {
                int br = wn * 32 + j * 8 + g;
                uint2 b0 = sB[buf][br][bp];
                uint2 b1 = sB[buf][br][bp + 4];
                mma_bf16(c[j], a0.x, a1.x, a2.x, a3.x, b0.x, b1.x);
                mma_bf16(c[j], a0.x, a1.x, a2.x, a3.x, b0.y, b1.y);
                mma_bf16(c[j], a0.y, a1.y, a2.y, a3.y, b0.x, b1.x);
            }
        }
        // stage next chunk into other buffer
        if (ch < 15) {
            int nb = buf ^ 1;
#pragma unroll
            for (int i = 0; i < 4; i++) {
                *reinterpret_cast<uint4*>(&sA[nb][s_rl[i]][s_plc[i]]) = pa[i];
                *reinterpret_cast<uint4*>(&sB[nb][s_r[i]][s_q[i]]) = pb[i];
            }
        }
        __syncthreads();
    }

#pragma unroll
    for (int j = 0; j < 4; j++) {
#pragma unroll
        for (int rh = 0; rh < 2; rh++) {
            int m = mbase + wm * 16 + g + rh * 8;
            int n = nbase + wn * 32 + j * 8 + 2 * tq;
            float v0 = c[j][rh * 2 + 0] + bias[n];
            float v1 = c[j][rh * 2 + 1] + bias[n + 1];
            if (mode == 0) {
                outf[(size_t)m * Hn + n] = v0;
                outf[(size_t)m * Hn + n + 1] = v1;
            } else {
                int b = m & (Bn - 1), t = m >> 7;
                size_t o = ((size_t)b * Tn + t) * Vn + n;
                outf[o] = v0;
                outf[o + 1] = v1;
            }
        }
    }
}

// ---------------- layernorm (fragment layout in/out) ------------------------
__global__ void __launch_bounds__(256) ln_kernel(
    const uint2* __restrict__ hp, const float* __restrict__ gam,
    const float* __restrict__ bet, uint2* __restrict__ nm)
{
    __shared__ float red[18];
    size_t row = blockIdx.x;
    int tid = threadIdx.x;
    int c0 = tid * 4;
    int p0 = tid * 2;
    size_t fo = (((size_t)(row >> 3)) * 128 + (p0 >> 2)) * 32 + ((int)row & 7) * 4 + (p0 & 3);

    uint4 in = *reinterpret_cast<const uint4*>(&hp[fo]);
    const __nv_bfloat162* pcs = reinterpret_cast<const __nv_bfloat162*>(&in);
    float v[4];
    v[0] = __bfloat162float(pcs[0].x) + __bfloat162float(pcs[1].x);
    v[1] = __bfloat162float(pcs[0].y) + __bfloat162float(pcs[1].y);
    v[2] = __bfloat162float(pcs[2].x) + __bfloat162float(pcs[3].x);
    v[3] = __bfloat162float(pcs[2].y) + __bfloat162float(pcs[3].y);

    float s = 0.f, q = 0.f;
#pragma unroll
    for (int i = 0; i < 4; i++) { s += v[i]; q += v[i] * v[i]; }
#pragma unroll
    for (int o = 16; o; o >>= 1) {
        s += __shfl_xor_sync(0xffffffffu, s, o);
        q += __shfl_xor_sync(0xffffffffu, q, o);
    }
    int warp = tid >> 5, lane = tid & 31;
    if (lane == 0) { red[warp] = s; red[warp + 8] = q; }
    __syncthreads();
    if (tid == 0) {
        float ss = 0.f, qq = 0.f;
#pragma unroll
        for (int i = 0; i < 8; i++) { ss += red[i]; qq += red[i + 8]; }
        float mu = ss / (float)Hn;
        float var = qq / (float)Hn - mu * mu;
        red[16] = mu;
        red[17] = rsqrtf(var + 1e-5f);
    }
    __syncthreads();
    float mu = red[16], rstd = red[17];

    bf16 hh[4], ll[4];
#pragma unroll
    for (int i = 0; i < 4; i++) {
        float nv = (v[i] - mu) * rstd * gam[c0 + i] + bet[c0 + i];
        hh[i] = __float2bfloat16(nv);
        ll[i] = __float2bfloat16(nv - __bfloat162float(hh[i]));
    }
    union { uint4 q4; __nv_bfloat162 h2[4]; } U;
    U.h2[0].x = hh[0]; U.h2[0].y = hh[1];
    U.h2[1].x = ll[0]; U.h2[1].y = ll[1];
    U.h2[2].x = hh[2]; U.h2[2].y = hh[3];
    U.h2[3].x = ll[2]; U.h2[3].y = ll[3];
    *reinterpret_cast<uint4*>(&nm[fo]) = U.q4;
}

// ---------------- launch ------------------------------------------------------
extern "C" void kernel_launch(void* const* d_in, const int* in_sizes, int n_in,
                              void* d_out, int out_size)
{
    const float* emb    = (const float*)d_in[0];
    const float* wi0    = (const float*)d_in[1];
    const float* bi0    = (const float*)d_in[2];
    const float* wh0    = (const float*)d_in[3];
    const float* wi1    = (const float*)d_in[4];
    const float* bi1    = (const float*)d_in[5];
    const float* wh1    = (const float*)d_in[6];
    const float* ln_g   = (const float*)d_in[7];
    const float* ln_b   = (const float*)d_in[8];
    const float* proj_w = (const float*)d_in[9];
    const float* proj_b = (const float*)d_in[10];
    const int*   x      = (const int*)d_in[11];

    uint2 *h1p, *h2p, *nmp, *wh0p, *wh1p, *wi1p, *pwp;
    float *xp1, *xpe;
    cudaGetSymbolAddress((void**)&h1p,  g_h1p);
    cudaGetSymbolAddress((void**)&h2p,  g_h2p);
    cudaGetSymbolAddress((void**)&nmp,  g_nmp);
    cudaGetSymbolAddress((void**)&wh0p, g_wh0p);
    cudaGetSymbolAddress((void**)&wh1p, g_wh1p);
    cudaGetSymbolAddress((void**)&wi1p, g_wi1p);
    cudaGetSymbolAddress((void**)&pwp,  g_pwp);
    cudaGetSymbolAddress((void**)&xp1,  g_xp1);
    cudaGetSymbolAddress((void**)&xpe,  g_xpe);

    cudaFuncSetAttribute(scan_reg_kernel,
                         cudaFuncAttributeMaxDynamicSharedMemorySize,
                         SCAN_SMEM_BYTES);

    // [0] flag reset (replay safety for the dataflow flags)
    reset_flags_kernel<<<(2 * 4 * 32 * 32 + 255) / 256, 256>>>();
    // [1],[2] setup; [3] scan0 (kept at ncu's profiled slot)
    split_pack_kernel<<<(Hn * HP + 255) / 256, 256>>>(wh0, wh0p, Hn * HP);
    xpe_kernel<<<dim3(16, 16), 256>>>(emb, wi0, bi0, xpe);

    scan_reg_kernel<<<dim3(32, 4), 512, SCAN_SMEM_BYTES>>>(
        wh0p, h1p, xpe, x, 0);

    split_pack_kernel<<<(Hn * HP + 255) / 256, 256>>>(wi1, wi1p, Hn * HP);
    gemm_split_kernel<<<dim3(1024, 16), 256>>>(h1p, wi1p, bi1, xp1, 0);

    split_pack_kernel<<<(Hn * HP + 255) / 256, 256>>>(wh1, wh1p, Hn * HP);
    scan_reg_kernel<<<dim3(32, 4), 512, SCAN_SMEM_BYTES>>>(
        wh1p, h2p, xp1, x, 1);

    split_pack_kernel<<<(Vn * HP + 255) / 256, 256>>>(proj_w, pwp, Vn * HP);
    ln_kernel<<<Tn * Bn, 256>>>(h2p, ln_g, ln_b, nmp);
    gemm_split_kernel<<<dim3(1024, 4), 256>>>(nmp, pwp, proj_b, (float*)d_out, 1);
}